// round 13
// baseline (speedup 1.0000x reference)
#include <cuda_runtime.h>
#include <cuda_bf16.h>
#include <cstdint>

#define BB 128
#define TT 1024
#define EE 512
#define HH 1024
#define VV 512
#define NB 128
#define NT 256
#define BH (BB*HH)
#define BTV ((size_t)BB*TT*VV)

#define AB0    131072          // A double buffer after persistent B (<=128KB)
#define ABSZ   32768
#define DYNB_ALLOC (AB0 + 2*ABSZ + 1024)

__device__ __align__(16) float g_tokproj[VV * HH];
__device__ __align__(16) float g_part[64][128 * 64];        // pairwise kc1 partials
__device__ __align__(16) __nv_bfloat16 g_h0ring[4][2][BH];  // slot x term
__device__ __align__(16) __nv_bfloat16 g_h1ring[4][2][BH];
__device__ __align__(16) __nv_bfloat16 g_w0sp[2][HH * HH];  // w_hh0
__device__ __align__(16) __nv_bfloat16 g_w1sp[2][HH * HH];  // w_xh1
__device__ __align__(16) __nv_bfloat16 g_w2sp[2][HH * HH];  // w_hh1
__device__ __align__(16) __nv_bfloat16 g_wysp[2][VV * HH];  // w_hy
__device__ unsigned long long g_br[8];
__device__ unsigned long long g_ep[NB];
__device__ unsigned long long g_flag[64];

__device__ __forceinline__ uint32_t smem_u32(const void* p) {
    uint32_t a;
    asm("{ .reg .u64 t; cvta.to.shared.u64 t, %1; cvt.u32.u64 %0, t; }" : "=r"(a) : "l"(p));
    return a;
}
__device__ __forceinline__ void cp16(uint32_t dst, const void* src) {
    asm volatile("cp.async.cg.shared.global [%0], [%1], 16;" :: "r"(dst), "l"(src) : "memory");
}
#define CP_COMMIT() asm volatile("cp.async.commit_group;" ::: "memory")
#define CP_WAIT1()  asm volatile("cp.async.wait_group 1;" ::: "memory")
#define CP_WAIT0()  asm volatile("cp.async.wait_group 0;" ::: "memory")
#define STS128(a, x, y, z, w) \
    asm volatile("st.shared.v4.b32 [%0], {%1,%2,%3,%4};" \
                 :: "r"(a), "r"(x), "r"(y), "r"(z), "r"(w) : "memory")
#define LDSM4(r, a) \
    asm volatile("ldmatrix.sync.aligned.m8n8.x4.shared.b16 {%0,%1,%2,%3}, [%4];" \
        : "=r"((r)[0]), "=r"((r)[1]), "=r"((r)[2]), "=r"((r)[3]) : "r"(a))
#define MMA16816(c, a, b0r, b1r) \
    asm volatile("mma.sync.aligned.m16n8k16.row.col.f32.bf16.bf16.f32 " \
        "{%0,%1,%2,%3}, {%4,%5,%6,%7}, {%8,%9}, {%0,%1,%2,%3};" \
        : "+f"((c)[0]), "+f"((c)[1]), "+f"((c)[2]), "+f"((c)[3]) \
        : "r"((a)[0]), "r"((a)[1]), "r"((a)[2]), "r"((a)[3]), "r"(b0r), "r"(b1r))

__device__ __forceinline__ void grid_bar(unsigned long long& ep) {
    ep += (unsigned long long)NB;
    __syncthreads();
    if (threadIdx.x == 0) {
        __threadfence();
        atomicAdd(&g_br[blockIdx.x & 7], 1ULL);
        for (;;) {
            unsigned long long s = 0;
#pragma unroll
            for (int i = 0; i < 8; i++) s += *(volatile unsigned long long*)&g_br[i];
            if (s >= ep) break;
            __nanosleep(32);
        }
        __threadfence();
    }
    __syncthreads();
}

__device__ __forceinline__ void split2(float x, __nv_bfloat16& d0, __nv_bfloat16& d1) {
    __nv_bfloat16 b0 = __float2bfloat16(x);
    d0 = b0;
    d1 = __float2bfloat16(x - __bfloat162float(b0));
}
// write (v0,v1) at columns (idx, idx+1) of both term arrays
__device__ __forceinline__ void st_split_pair(__nv_bfloat16* d0, __nv_bfloat16* d1,
                                              size_t idx, float v0, float v1) {
    __nv_bfloat16 a0, b0, a1, b1;
    split2(v0, a0, b0); split2(v1, a1, b1);
    __nv_bfloat162 t0(a0, a1), t1(b0, b1);
    *(uint32_t*)(d0 + idx) = *(uint32_t*)&t0;
    *(uint32_t*)(d1 + idx) = *(uint32_t*)&t1;
}

// SIMT fp32 64x64 GEMM (tokproj prologue only)
template <typename LA, typename LB, typename ST>
__device__ __forceinline__ void gemm64(float* sA, float* sB, int kend, LA la, LB lb, ST st) {
    const int tid = threadIdx.x;
    const int tx = tid & 15, ty = tid >> 4;
    float acc[4][4];
#pragma unroll
    for (int i = 0; i < 4; i++)
#pragma unroll
        for (int j = 0; j < 4; j++) acc[i][j] = 0.f;
    for (int k0 = 0; k0 < kend; k0 += 32) {
#pragma unroll
        for (int i = 0; i < 8; i++) {
            int idx = tid + i * NT;
            int k = idx & 31, r = idx >> 5;
            sA[k * 68 + r] = la(r, k0 + k);
            sB[k * 68 + r] = lb(r, k0 + k);
        }
        __syncthreads();
#pragma unroll
        for (int kk = 0; kk < 32; kk++) {
            float4 a = *(const float4*)(sA + kk * 68 + 4 * ty);
            float4 b = *(const float4*)(sB + kk * 68 + 4 * tx);
            float av[4] = {a.x, a.y, a.z, a.w};
            float bv[4] = {b.x, b.y, b.z, b.w};
#pragma unroll
            for (int i = 0; i < 4; i++)
#pragma unroll
                for (int j = 0; j < 4; j++) acc[i][j] = fmaf(av[i], bv[j], acc[i][j]);
        }
        __syncthreads();
    }
#pragma unroll
    for (int i = 0; i < 4; i++)
        st(4 * ty + i, 4 * tx, make_float4(acc[i][0], acc[i][1], acc[i][2], acc[i][3]));
}

// stage one A chunk: 2 terms x 128 rows x 64 K-cols -> 32KB
__device__ __forceinline__ void stage_a(uint32_t ab, const __nv_bfloat16* A0,
                                        const __nv_bfloat16* A1, int kg) {
    const int tid = threadIdx.x;
#pragma unroll
    for (int it = 0; it < 8; it++) {
        int id = tid + it * NT;
        int i = id >> 10, rem = id & 1023, r = rem >> 3, seg = rem & 7;
        const __nv_bfloat16* s = (i ? A1 : A0) + (size_t)r * HH + kg + seg * 8;
        cp16(ab + i * 16384 + r * 128 + ((seg ^ (r & 7)) << 4), s);
    }
    CP_COMMIT();
}

// K=64 chunk, N=64 job: 8 warps = 2M(64) x 4N(16)
__device__ __forceinline__ void chunk_n64(float acc[4][2][4], uint32_t ab, uint32_t pb,
                                          int wm, int wn, int lane) {
#pragma unroll
    for (int kk = 0; kk < 4; kk++) {
        uint32_t af[2][4][4];
#pragma unroll
        for (int tm = 0; tm < 2; tm++)
#pragma unroll
            for (int mt = 0; mt < 4; mt++) {
                int row = wm * 64 + mt * 16 + (lane & 15);
                int ch = kk * 2 + (lane >> 4);
                LDSM4(af[tm][mt], ab + tm * 16384 + row * 128 + ((ch ^ (row & 7)) << 4));
            }
        uint32_t bf[2][4];
#pragma unroll
        for (int j = 0; j < 2; j++) {
            int nrow = wn * 16 + (lane & 7) + ((lane & 16) ? 8 : 0);
            int ch = kk * 2 + ((lane >> 3) & 1);
            LDSM4(bf[j], pb + j * 8192 + nrow * 128 + ((ch ^ (nrow & 7)) << 4));
        }
#pragma unroll
        for (int j = 0; j < 2; j++) {
            const int ni = (j == 0) ? 2 : 1;
#pragma unroll
            for (int i = 0; i < 2; i++) {
                if (i >= ni) break;
#pragma unroll
                for (int mt = 0; mt < 4; mt++)
#pragma unroll
                    for (int nt = 0; nt < 2; nt++)
                        MMA16816(acc[mt][nt], af[i][mt], bf[j][nt * 2], bf[j][nt * 2 + 1]);
            }
        }
    }
}

// K=64 chunk, N=32 job: 8 warps = 4M(32) x 2N(16)
__device__ __forceinline__ void chunk_n32(float acc[2][2][4], uint32_t ab, uint32_t pb,
                                          int wm, int wn, int lane) {
#pragma unroll
    for (int kk = 0; kk < 4; kk++) {
        uint32_t af[2][2][4];
#pragma unroll
        for (int tm = 0; tm < 2; tm++)
#pragma unroll
            for (int mt = 0; mt < 2; mt++) {
                int row = wm * 32 + mt * 16 + (lane & 15);
                int ch = kk * 2 + (lane >> 4);
                LDSM4(af[tm][mt], ab + tm * 16384 + row * 128 + ((ch ^ (row & 7)) << 4));
            }
        uint32_t bf[2][4];
#pragma unroll
        for (int j = 0; j < 2; j++) {
            int nrow = wn * 16 + (lane & 7) + ((lane & 16) ? 8 : 0);
            int ch = kk * 2 + ((lane >> 3) & 1);
            LDSM4(bf[j], pb + j * 4096 + nrow * 128 + ((ch ^ (nrow & 7)) << 4));
        }
#pragma unroll
        for (int j = 0; j < 2; j++) {
            const int ni = (j == 0) ? 2 : 1;
#pragma unroll
            for (int i = 0; i < 2; i++) {
                if (i >= ni) break;
#pragma unroll
                for (int mt = 0; mt < 2; mt++)
#pragma unroll
                    for (int nt = 0; nt < 2; nt++)
                        MMA16816(acc[mt][nt], af[i][mt], bf[j][nt * 2], bf[j][nt * 2 + 1]);
            }
        }
    }
}

__global__ void __launch_bounds__(NT, 1) rnn_mma_kernel(
    const int*   __restrict__ ids,   const float* __restrict__ emb,
    const float* __restrict__ w_xh0, const float* __restrict__ w_hh0,
    const float* __restrict__ b_h0,  const float* __restrict__ w_xh1,
    const float* __restrict__ w_hh1, const float* __restrict__ b_h1,
    const float* __restrict__ w_hy,  const float* __restrict__ b_y,
    float* __restrict__ out, long long out_size)
{
    extern __shared__ __align__(16) char dynsm[];
    const int bid = blockIdx.x;
    const int tid = threadIdx.x;
    const int lane = tid & 31;
    const int warp = tid >> 5;
    const uint32_t dyn = (smem_u32(dynsm) + 1023u) & ~1023u;
    const long long full = (long long)BTV + 2LL * BH;

    unsigned long long ep = g_ep[bid];

    // ---- roles: pairwise kc split; kc0 owns combine ----
    // P0 : bid  0..31  : 16 n-slices(64) x kc2, K=512 each  (h0 @ w_hh0^T)
    // P1 : bid 32..95  : 32 n-slices(32) x kc2; kc0=h0@w_xh1^T(K=1024), kc1=h1@w_hh1^T(K=1024)
    // Py : bid 96..127 : 16 n-slices(32) x kc2, K=512 each  (h1 @ w_hy^T)
    int role, ns, kc, n0, nch, pairid;
    if (bid < 32)       { role = 0; ns = bid >> 1;        kc = bid & 1; n0 = ns * 64; nch = 8;  pairid = ns; }
    else if (bid < 96)  { role = 1; ns = (bid - 32) >> 1; kc = bid & 1; n0 = ns * 32; nch = 16; pairid = 16 + ns; }
    else                { role = 2; ns = (bid - 96) >> 1; kc = bid & 1; n0 = ns * 32; nch = 8;  pairid = 48 + ns; }
    const int ncols = (role == 0) ? 64 : 32;
    // flag base (read BEFORE prologue bar -> replay-safe)
    unsigned long long fbase = 0;
    if (kc == 0) fbase = *(volatile unsigned long long*)&g_flag[pairid];

    // ============ prologue ============
    {
        const float* W[4] = {w_hh0, w_xh1, w_hh1, w_hy};
        __nv_bfloat16* S0[4] = {g_w0sp[0], g_w1sp[0], g_w2sp[0], g_wysp[0]};
        __nv_bfloat16* S1[4] = {g_w0sp[1], g_w1sp[1], g_w2sp[1], g_wysp[1]};
        const int SZ[4] = {HH * HH, HH * HH, HH * HH, VV * HH};
#pragma unroll
        for (int w = 0; w < 4; w++)
            for (int i = bid * NT + tid; i < SZ[w]; i += NB * NT)
                split2(W[w][i], S0[w][i], S1[w][i]);
        for (int i = bid * NT + tid; i < BH; i += NB * NT) {   // h1_{-1}=0 in slot 3
            g_h1ring[3][0][i] = __float2bfloat16(0.f);
            g_h1ring[3][1][i] = __float2bfloat16(0.f);
        }
    }
    {
        float* sA = (float*)dynsm;
        float* sB = sA + 32 * 68;
        int m0 = (bid & 7) * 64, n0t = (bid >> 3) * 64;
        gemm64(sA, sB, EE,
            [&](int r, int k) { return emb[(m0 + r) * EE + k]; },
            [&](int r, int k) { return w_xh0[(n0t + r) * EE + k]; },
            [&](int m, int n, float4 v) {
                int col = n0t + n;
                float4 bb = *(const float4*)(b_h0 + col);
                v.x += bb.x; v.y += bb.y; v.z += bb.z; v.w += bb.w;
                *(float4*)(g_tokproj + (size_t)(m0 + m) * HH + col) = v;
            });
    }
    grid_bar(ep);

    // ---- persistent B slab + h0(0) ----
    {
        const __nv_bfloat16 *S0, *S1;
        int koff = 0;
        if (role == 0)      { S0 = g_w0sp[0]; S1 = g_w0sp[1]; koff = kc * 512; }
        else if (role == 1) { S0 = kc ? g_w2sp[0] : g_w1sp[0]; S1 = kc ? g_w2sp[1] : g_w1sp[1]; }
        else                { S0 = g_wysp[0]; S1 = g_wysp[1]; koff = kc * 512; }
        if (role == 0) {
            for (int x = tid; x < 8192; x += NT) {            // 8 chunks x 1024 uint4
                int c = x >> 10, rem = x & 1023, j = rem >> 9, r = (rem >> 3) & 63, seg = x & 7;
                const __nv_bfloat16* s = (j ? S1 : S0)
                    + (size_t)(n0 + r) * HH + koff + c * 64 + seg * 8;
                uint4 v = *(const uint4*)s;
                STS128(dyn + c * 16384 + j * 8192 + r * 128 + ((seg ^ (r & 7)) << 4),
                       v.x, v.y, v.z, v.w);
            }
        } else {
            for (int x = tid; x < nch * 512; x += NT) {       // nch chunks x 512 uint4
                int c = x >> 9, rem = x & 511, j = rem >> 8, r = (rem >> 3) & 31, seg = x & 7;
                const __nv_bfloat16* s = (j ? S1 : S0)
                    + (size_t)(n0 + r) * HH + koff + c * 64 + seg * 8;
                uint4 v = *(const uint4*)s;
                STS128(dyn + c * 8192 + j * 4096 + r * 128 + ((seg ^ (r & 7)) << 4),
                       v.x, v.y, v.z, v.w);
            }
        }
        // h0(0) = tanh(tokproj[ids[:,0]])  (one float4 per thread grid-wide)
        int idx4 = (bid * NT + tid) * 4;
        int row = idx4 >> 10, h = idx4 & 1023;
        float4 s = *(const float4*)(g_tokproj + (size_t)ids[row * TT] * HH + h);
        size_t idx = (size_t)row * HH + h;
        st_split_pair(g_h0ring[0][0], g_h0ring[0][1], idx, tanhf(s.x), tanhf(s.y));
        st_split_pair(g_h0ring[0][0], g_h0ring[0][1], idx + 2, tanhf(s.z), tanhf(s.w));
        __syncthreads();
    }
    grid_bar(ep);

    // ============ main loop: one barrier per step ============
    float* mypart = &g_part[pairid][0];
    unsigned long long cnt = 0;
    const int wmA = warp >> 2, wnA = warp & 3;   // n64 mapping
    const int wmB = warp >> 1, wnB = warp & 1;   // n32 mapping

    for (int t = 0; t <= TT + 1; t++) {
        bool valid = (role == 0) ? (t <= TT - 2)
                   : (role == 1) ? (t <= TT - 1)
                                 : (t >= 2 && t <= TT + 1);
        if (valid) {
            const __nv_bfloat16 *A0, *A1;
            int kbeg;
            if (role == 0)      { A0 = g_h0ring[t & 3][0]; A1 = g_h0ring[t & 3][1]; kbeg = kc * 512; }
            else if (role == 1) {
                int slot = kc ? ((t - 1) & 3) : (t & 3);
                A0 = kc ? g_h1ring[slot][0] : g_h0ring[slot][0];
                A1 = kc ? g_h1ring[slot][1] : g_h0ring[slot][1];
                kbeg = 0;
            } else              { A0 = g_h1ring[(t - 2) & 3][0]; A1 = g_h1ring[(t - 2) & 3][1]; kbeg = kc * 512; }

            float acc64[4][2][4];
            float acc32[2][2][4];
            if (role == 0) {
#pragma unroll
                for (int a = 0; a < 4; a++)
#pragma unroll
                    for (int b = 0; b < 2; b++)
#pragma unroll
                        for (int c = 0; c < 4; c++) acc64[a][b][c] = 0.f;
            } else {
#pragma unroll
                for (int a = 0; a < 2; a++)
#pragma unroll
                    for (int b = 0; b < 2; b++)
#pragma unroll
                        for (int c = 0; c < 4; c++) acc32[a][b][c] = 0.f;
            }
            stage_a(dyn + AB0, A0, A1, kbeg);
            stage_a(dyn + AB0 + ABSZ, A0, A1, kbeg + 64);
            const int bch = (role == 0) ? 16384 : 8192;
            for (int c = 0; c < nch; c++) {
                if (c + 1 < nch) { CP_WAIT1(); } else { CP_WAIT0(); }
                __syncthreads();
                if (role == 0)
                    chunk_n64(acc64, dyn + AB0 + (c & 1) * ABSZ, dyn + c * bch, wmA, wnA, lane);
                else
                    chunk_n32(acc32, dyn + AB0 + (c & 1) * ABSZ, dyn + c * bch, wmB, wnB, lane);
                __syncthreads();
                if (c + 2 < nch) stage_a(dyn + AB0 + (c & 1) * ABSZ, A0, A1, kbeg + (c + 2) * 64);
            }

            if (kc == 1) {
                // store partial, raise flag
                if (role == 0) {
#pragma unroll
                    for (int mt = 0; mt < 4; mt++)
#pragma unroll
                        for (int nt = 0; nt < 2; nt++) {
                            int r = wmA * 64 + mt * 16 + (lane >> 2);
                            int cc = wnA * 16 + nt * 8 + (lane & 3) * 2;
                            __stcg((float2*)(mypart + r * 64 + cc),
                                   make_float2(acc64[mt][nt][0], acc64[mt][nt][1]));
                            __stcg((float2*)(mypart + (r + 8) * 64 + cc),
                                   make_float2(acc64[mt][nt][2], acc64[mt][nt][3]));
                        }
                } else {
#pragma unroll
                    for (int mt = 0; mt < 2; mt++)
#pragma unroll
                        for (int nt = 0; nt < 2; nt++) {
                            int r = wmB * 32 + mt * 16 + (lane >> 2);
                            int cc = wnB * 16 + nt * 8 + (lane & 3) * 2;
                            __stcg((float2*)(mypart + r * 32 + cc),
                                   make_float2(acc32[mt][nt][0], acc32[mt][nt][1]));
                            __stcg((float2*)(mypart + (r + 8) * 32 + cc),
                                   make_float2(acc32[mt][nt][2], acc32[mt][nt][3]));
                        }
                }
                __syncthreads();
                if (tid == 0) {
                    __threadfence();
                    atomicAdd(&g_flag[pairid], 1ULL);
                }
            } else {
                // wait partner, combine, publish
                if (tid == 0) {
                    while (*(volatile unsigned long long*)&g_flag[pairid] < fbase + cnt + 1) {
                        __nanosleep(32);
                    }
                    __threadfence();
                }
                __syncthreads();
                if (role == 0) {
                    __nv_bfloat16* D0 = g_h0ring[(t + 1) & 3][0];
                    __nv_bfloat16* D1 = g_h0ring[(t + 1) & 3][1];
#pragma unroll
                    for (int mt = 0; mt < 4; mt++)
#pragma unroll
                        for (int nt = 0; nt < 2; nt++) {
#pragma unroll
                            for (int hh = 0; hh < 2; hh++) {
                                int r = wmA * 64 + mt * 16 + (lane >> 2) + hh * 8;
                                int cc = wnA * 16 + nt * 8 + (lane & 3) * 2;
                                float2 pp = __ldcg((const float2*)(mypart + r * 64 + cc));
                                int id1 = ids[r * TT + t + 1];
                                float2 tp = *(const float2*)(g_tokproj + (size_t)id1 * HH + n0 + cc);
                                float v0 = tanhf(acc64[mt][nt][hh * 2] + pp.x + tp.x);
                                float v1 = tanhf(acc64[mt][nt][hh * 2 + 1] + pp.y + tp.y);
                                size_t idx = (size_t)r * HH + n0 + cc;
                                st_split_pair(D0, D1, idx, v0, v1);
                                if (t == TT - 2 && out_size >= full)
                                    *(float2*)&out[BTV + idx] = make_float2(v0, v1);
                            }
                        }
                } else if (role == 1) {
                    __nv_bfloat16* D0 = g_h1ring[t & 3][0];
                    __nv_bfloat16* D1 = g_h1ring[t & 3][1];
#pragma unroll
                    for (int mt = 0; mt < 2; mt++)
#pragma unroll
                        for (int nt = 0; nt < 2; nt++) {
#pragma unroll
                            for (int hh = 0; hh < 2; hh++) {
                                int r = wmB * 32 + mt * 16 + (lane >> 2) + hh * 8;
                                int cc = wnB * 16 + nt * 8 + (lane & 3) * 2;
                                float2 pp = __ldcg((const float2*)(mypart + r * 32 + cc));
                                float2 bb = *(const float2*)(b_h1 + n0 + cc);
                                float v0 = tanhf(acc32[mt][nt][hh * 2] + pp.x + bb.x);
                                float v1 = tanhf(acc32[mt][nt][hh * 2 + 1] + pp.y + bb.y);
                                size_t idx = (size_t)r * HH + n0 + cc;
                                st_split_pair(D0, D1, idx, v0, v1);
                                if (t == TT - 1 && out_size >= full)
                                    *(float2*)&out[BTV + BH + idx] = make_float2(v0, v1);
                            }
                        }
                } else {
#pragma unroll
                    for (int mt = 0; mt < 2; mt++)
#pragma unroll
                        for (int nt = 0; nt < 2; nt++) {
#pragma unroll
                            for (int hh = 0; hh < 2; hh++) {
                                int r = wmB * 32 + mt * 16 + (lane >> 2) + hh * 8;
                                int cc = wnB * 16 + nt * 8 + (lane & 3) * 2;
                                float2 pp = __ldcg((const float2*)(mypart + r * 32 + cc));
                                float2 bb = *(const float2*)(b_y + n0 + cc);
                                float v0 = acc32[mt][nt][hh * 2] + pp.x + bb.x;
                                float v1 = acc32[mt][nt][hh * 2 + 1] + pp.y + bb.y;
                                *(float2*)&out[((size_t)r * TT + (t - 2)) * VV + n0 + cc] =
                                    make_float2(v0, v1);
                            }
                        }
                }
            }
            cnt++;
        }
        grid_bar(ep);
    }

    if (tid == 0) g_ep[bid] = ep;
}

extern "C" void kernel_launch(void* const* d_in, const int* in_sizes, int n_in,
                              void* d_out, int out_size) {
    const int*   ids   = (const int*)d_in[0];
    const float* emb   = (const float*)d_in[1];
    const float* w_xh0 = (const float*)d_in[2];
    const float* w_hh0 = (const float*)d_in[3];
    const float* b_h0  = (const float*)d_in[4];
    const float* w_xh1 = (const float*)d_in[5];
    const float* w_hh1 = (const float*)d_in[6];
    const float* b_h1  = (const float*)d_in[7];
    const float* w_hy  = (const float*)d_in[8];
    const float* b_y   = (const float*)d_in[9];
    float* out = (float*)d_out;

    cudaFuncSetAttribute(rnn_mma_kernel, cudaFuncAttributeMaxDynamicSharedMemorySize,
                         DYNB_ALLOC);
    rnn_mma_kernel<<<NB, NT, DYNB_ALLOC>>>(ids, emb, w_xh0, w_hh0, b_h0,
                                           w_xh1, w_hh1, b_h1, w_hy, b_y,
                                           out, (long long)out_size);
}